// round 16
// baseline (speedup 1.0000x reference)
#include <cuda_runtime.h>

// GINConv fused: out = A @ (X @ W)  (reassociated from (A@X) @ W)
// N=100000 nodes, E=2.5M edges (CSR), D_IN = D_OUT = 32.
// R16: prep computes Y=X@W (+zero out) and a COMPACT per-edge row encoding:
//   g_warpstart[chunk] (int) + g_rowoff8[edge] (uint8 offset from chunk start).
// Aggregate does zero searching: row = warpstart + byte. MLP-8 batched
// gathers, segmented red.global.add.v4.f32 flushes.

#define MAX_N 100000
#define MAX_E 2600000
#define D 32
#define MAX_CHUNKS ((MAX_E + 31) / 32)

// Scratch (static to obey no-alloc rule):
__device__ __align__(16) float g_Y[MAX_N * D];        // Y = X @ W (12.8 MB)
__device__ int g_warpstart[MAX_CHUNKS];               // row of first edge per chunk
__device__ __align__(16) unsigned char g_rowoff8[MAX_CHUNKS * 32]; // 2.5 MB

// packed f32x2 accumulate: a += b (two fp32 adds in one instruction)
__device__ __forceinline__ void add2(unsigned long long& a, unsigned long long b) {
    asm("add.rn.f32x2 %0, %0, %1;" : "+l"(a) : "l"(b));
}

__device__ __forceinline__ void flush_v4(float* p, unsigned long long a01,
                                         unsigned long long a23) {
    asm volatile("red.global.add.v4.f32 [%0], {%1, %2, %3, %4};"
        :: "l"(p),
           "f"(__uint_as_float((unsigned)a01)),
           "f"(__uint_as_float((unsigned)(a01 >> 32))),
           "f"(__uint_as_float((unsigned)a23)),
           "f"(__uint_as_float((unsigned)(a23 >> 32)))
        : "memory");
}

// ---------------------------------------------------------------------------
// Kernel 1 (role-split by block):
//   blocks [0, tblocks):       Y = X @ W, zero-init `out` (4 rows/warp)
//   blocks [tblocks, gridDim): per-chunk row table: binary-search the chunk's
//     start row, then serially walk rp to emit 32 uint8 row offsets.
// ---------------------------------------------------------------------------
__global__ void __launch_bounds__(256) gin_prep(
    const float* __restrict__ X, const float* __restrict__ W,
    const int* __restrict__ rp, float* __restrict__ out,
    int n, int tblocks, int nchunks, int nedges)
{
    __shared__ __align__(16) float Ws[D * D];
    __shared__ __align__(16) float Xs[8][4 * 36];

    int tid = threadIdx.x;

    if (blockIdx.x >= tblocks) {
        // ---- row-table role: one thread per 32-edge chunk ----
        int c = (blockIdx.x - tblocks) * 256 + tid;
        if (c < nchunks) {
            int e0 = c * 32;
            // sr = largest r with rp[r] <= e0
            int lo = 0, hi = n - 1;
            #pragma unroll 1
            while (lo < hi) {
                int mid = (lo + hi + 1) >> 1;
                if (__ldg(&rp[mid]) <= e0) lo = mid; else hi = mid - 1;
            }
            int sr = lo;
            g_warpstart[c] = sr;

            // Walk rp forward; off(e) = row(e) - sr, capped at 255 (fallback).
            unsigned off[8];                   // 32 bytes packed 4-per-word
            int idx = sr + 1;                  // candidate rp index
            int curoff = 0;
            #pragma unroll 1
            for (int j = 0; j < 32; j++) {
                int e = e0 + j;
                if (e < nedges) {
                    #pragma unroll 1
                    while (idx <= n && curoff < 255 && __ldg(&rp[idx]) <= e) {
                        idx++; curoff++;
                    }
                }
                unsigned b = (unsigned)curoff;
                if (curoff >= 255) b = 255;    // rare: aggregate re-searches
                if ((j & 3) == 0) off[j >> 2] = b;
                else off[j >> 2] |= b << ((j & 3) * 8);
            }
            uint4 lo4 = make_uint4(off[0], off[1], off[2], off[3]);
            uint4 hi4 = make_uint4(off[4], off[5], off[6], off[7]);
            ((uint4*)g_rowoff8)[c * 2]     = lo4;
            ((uint4*)g_rowoff8)[c * 2 + 1] = hi4;
        }
        return;
    }

    // ---- transform role ----
    for (int i = tid; i < D * D; i += 256) Ws[i] = W[i];
    __syncthreads();

    int lane = tid & 31;
    int wip  = tid >> 5;
    int warp = blockIdx.x * 8 + wip;
    int row4 = warp * 4;
    if (row4 >= n) return;

    int g = lane >> 3, s = lane & 7;
    int r = row4 + g;
    bool rv = (r < n);

    float4 xv = make_float4(0.f, 0.f, 0.f, 0.f);
    if (rv) xv = ((const float4*)X)[r * 8 + s];          // coalesced 512B/warp
    float* xrow = &Xs[wip][g * 36];
    *((float4*)(xrow + s * 4)) = xv;
    __syncwarp();

    float4 acc = make_float4(0.f, 0.f, 0.f, 0.f);
    #pragma unroll
    for (int k = 0; k < D; k++) {
        float  xk = xrow[k];
        float4 wr = ((const float4*)Ws)[k * 8 + s];      // LDS.128 broadcast
        acc.x = fmaf(xk, wr.x, acc.x);
        acc.y = fmaf(xk, wr.y, acc.y);
        acc.z = fmaf(xk, wr.z, acc.z);
        acc.w = fmaf(xk, wr.w, acc.w);
    }
    if (rv) {
        ((float4*)g_Y)[r * 8 + s] = acc;                 // coalesced 512B/warp
        ((float4*)out)[r * 8 + s] = make_float4(0.f, 0.f, 0.f, 0.f);
    }
}

// ---------------------------------------------------------------------------
// Kernel 2: edge-balanced aggregate. Warp w owns edges [32w, 32w+32).
// row(e) = g_warpstart[w] + g_rowoff8[e]  (one uniform int + one coalesced
// byte load; 255 -> rare global-search fallback). Stage (col,row) in smem;
// PHASE A batches 8 gather LDG.128s (MLP=8, 4 edges per warp-instruction);
// PHASE B segmented-accumulates, flushing runs with red.global.add.v4.f32.
// ---------------------------------------------------------------------------
__global__ void __launch_bounds__(256) gin_aggregate(
    const int* __restrict__ rp, const int* __restrict__ ci,
    float* __restrict__ out, int n, int nedges, int nchunks)
{
    __shared__ __align__(8) int2 pairs[8][32];

    int tid  = threadIdx.x;
    int lane = tid & 31;
    int wip  = tid >> 5;
    int grp  = lane >> 3, sub = lane & 7;
    int warp = blockIdx.x * 8 + wip;

    int e = warp * 32 + lane;
    bool valid = (e < nedges) && (warp < nchunks);

    int myc = 0, myrow = -1;
    if (valid) {
        myc = __ldg(&ci[e]);                           // coalesced
        int sr  = __ldg(&g_warpstart[warp]);           // uniform
        unsigned off = g_rowoff8[e];                   // coalesced 32B/warp
        if (off < 255u) {
            myrow = sr + (int)off;
        } else {                                       // rare fallback
            int lo = sr, hi = n - 1;
            #pragma unroll 1
            while (lo < hi) {
                int mid = (lo + hi + 1) >> 1;
                if (__ldg(&rp[mid]) <= e) lo = mid; else hi = mid - 1;
            }
            myrow = lo;
        }
    }

    int2 p; p.x = myc; p.y = myrow;
    pairs[wip][lane] = p;
    __syncwarp();

    const ulonglong2* __restrict__ Y2 = (const ulonglong2*)g_Y;  // row = 8x16B

    // PHASE A: batch all 8 independent gathers (1 LDG.128 = 4 edges/warp)
    ulonglong2 v[8];
    int rows[8];
    #pragma unroll
    for (int k = 0; k < 8; k++) {
        int2 q = pairs[wip][grp * 8 + k];              // broadcast LDS.64
        rows[k] = q.y;
        v[k] = __ldg(&Y2[(size_t)q.x * 8 + sub]);
    }

    // PHASE B: segmented accumulate over the 8 edges of this group
    unsigned long long a01 = 0ull, a23 = 0ull;
    int cur = -1;
    #pragma unroll
    for (int k = 0; k < 8; k++) {
        int r = rows[k];
        if (r < 0) continue;                           // tail sentinel
        if (r != cur) {
            if (cur >= 0)
                flush_v4(out + (size_t)cur * D + sub * 4, a01, a23);
            cur = r; a01 = 0ull; a23 = 0ull;
        }
        add2(a01, v[k].x);
        add2(a23, v[k].y);
    }
    if (cur >= 0)
        flush_v4(out + (size_t)cur * D + sub * 4, a01, a23);
}

// ---------------------------------------------------------------------------
extern "C" void kernel_launch(void* const* d_in, const int* in_sizes, int n_in,
                              void* d_out, int out_size)
{
    const float* X  = (const float*)d_in[0];
    const float* W  = (const float*)d_in[1];
    const int*   rp = (const int*)d_in[2];
    const int*   ci = (const int*)d_in[3];
    float*       out = (float*)d_out;

    int n      = in_sizes[0] / D;   // number of nodes
    int nedges = in_sizes[3];       // E

    const int THREADS = 256;
    int tblocks = (n + 31) / 32;                 // transform: 4 rows/warp
    int nchunks = (nedges + 31) / 32;            // 32 edges per warp
    int wblocks = (nchunks + 255) / 256;         // row-table role
    int ablocks = (nchunks + 7) / 8;             // aggregate: 8 warps/block

    gin_prep<<<tblocks + wblocks, THREADS>>>(X, W, rp, out, n, tblocks,
                                             nchunks, nedges);
    gin_aggregate<<<ablocks, THREADS>>>(rp, ci, out, n, nedges, nchunks);
}

// round 17
// speedup vs baseline: 1.7590x; 1.7590x over previous
#include <cuda_runtime.h>

// GINConv fused: out = A @ (X @ W)  (reassociated from (A@X) @ W)
// N=100000 nodes, E=2.5M edges (CSR), D_IN = D_OUT = 32.
// R17: prep (R12 form) = transform Y=X@W + zero out + per-chunk start rows.
// Aggregate: PERSISTENT grid-stride warps, software-pipelined: next chunk's
// index loads + row search overlap current chunk's MLP-8 gathers.

#define MAX_N 100000
#define MAX_E 2600000
#define D 32
#define MAX_CHUNKS ((MAX_E + 31) / 32)

// Scratch (static to obey no-alloc rule):
__device__ __align__(16) float g_Y[MAX_N * D];   // Y = X @ W (12.8 MB, L2-resident)
__device__ int g_warpstart[MAX_CHUNKS];          // row of first edge per chunk

// packed f32x2 accumulate: a += b (two fp32 adds in one instruction)
__device__ __forceinline__ void add2(unsigned long long& a, unsigned long long b) {
    asm("add.rn.f32x2 %0, %0, %1;" : "+l"(a) : "l"(b));
}

__device__ __forceinline__ void flush_v4(float* p, unsigned long long a01,
                                         unsigned long long a23) {
    asm volatile("red.global.add.v4.f32 [%0], {%1, %2, %3, %4};"
        :: "l"(p),
           "f"(__uint_as_float((unsigned)a01)),
           "f"(__uint_as_float((unsigned)(a01 >> 32))),
           "f"(__uint_as_float((unsigned)a23)),
           "f"(__uint_as_float((unsigned)(a23 >> 32)))
        : "memory");
}

// ---------------------------------------------------------------------------
// Kernel 1 (role-split by block):
//   blocks [0, tblocks):       Y = X @ W, zero-init `out` (4 rows/warp)
//   blocks [tblocks, gridDim): g_warpstart[c] = row(32c) via binary search
// ---------------------------------------------------------------------------
__global__ void __launch_bounds__(256) gin_prep(
    const float* __restrict__ X, const float* __restrict__ W,
    const int* __restrict__ rp, float* __restrict__ out,
    int n, int tblocks, int nchunks)
{
    __shared__ __align__(16) float Ws[D * D];
    __shared__ __align__(16) float Xs[8][4 * 36];

    int tid = threadIdx.x;

    if (blockIdx.x >= tblocks) {
        int c = (blockIdx.x - tblocks) * 256 + tid;
        if (c < nchunks) {
            int e0 = c * 32;
            int lo = 0, hi = n - 1;            // largest r with rp[r] <= e0
            #pragma unroll 1
            while (lo < hi) {
                int mid = (lo + hi + 1) >> 1;
                if (__ldg(&rp[mid]) <= e0) lo = mid; else hi = mid - 1;
            }
            g_warpstart[c] = lo;
        }
        return;
    }

    // ---- transform role ----
    for (int i = tid; i < D * D; i += 256) Ws[i] = W[i];
    __syncthreads();

    int lane = tid & 31;
    int wip  = tid >> 5;
    int warp = blockIdx.x * 8 + wip;
    int row4 = warp * 4;
    if (row4 >= n) return;

    int g = lane >> 3, s = lane & 7;
    int r = row4 + g;
    bool rv = (r < n);

    float4 xv = make_float4(0.f, 0.f, 0.f, 0.f);
    if (rv) xv = ((const float4*)X)[r * 8 + s];          // coalesced 512B/warp
    float* xrow = &Xs[wip][g * 36];
    *((float4*)(xrow + s * 4)) = xv;
    __syncwarp();

    float4 acc = make_float4(0.f, 0.f, 0.f, 0.f);
    #pragma unroll
    for (int k = 0; k < D; k++) {
        float  xk = xrow[k];
        float4 wr = ((const float4*)Ws)[k * 8 + s];      // LDS.128 broadcast
        acc.x = fmaf(xk, wr.x, acc.x);
        acc.y = fmaf(xk, wr.y, acc.y);
        acc.z = fmaf(xk, wr.z, acc.z);
        acc.w = fmaf(xk, wr.w, acc.w);
    }
    if (rv) {
        ((float4*)g_Y)[r * 8 + s] = acc;                 // coalesced 512B/warp
        ((float4*)out)[r * 8 + s] = make_float4(0.f, 0.f, 0.f, 0.f);
    }
}

// ---------------------------------------------------------------------------
// Stage for chunk c: lane's (column, destination-row) for edge 32c+lane.
// One coalesced ci load, uniform warpstart load, coalesced rp window load,
// 6-step shfl binary search over positions [0,32] (rare >32-row fallback).
// ---------------------------------------------------------------------------
__device__ __forceinline__ void stage_load(
    int c, int lane, const int* __restrict__ rp, const int* __restrict__ ci,
    int n, int nedges, int& myc, int& myrow)
{
    int e = c * 32 + lane;
    bool valid = (e < nedges);
    int ec = valid ? e : nedges - 1;

    myc = valid ? __ldg(&ci[e]) : 0;

    int sr = __ldg(&g_warpstart[c]);

    int widx = sr + 1 + lane;
    int wv = (widx <= n) ? __ldg(&rp[widx]) : 0x7fffffff;

    // first position p in [0,32] with wv[p] > ec (33 outcomes -> 6 steps)
    int lo = 0, hi = 32;
    #pragma unroll
    for (int it = 0; it < 6; it++) {
        int mid = (lo + hi) >> 1;
        int v = __shfl_sync(0xffffffffu, wv, mid & 31);
        if (lo < hi) { if (v <= ec) lo = mid + 1; else hi = mid; }
    }
    myrow = sr + lo;

    if (lo == 32) {                            // rare: chunk spans >32 rows
        int slo = sr + 32, shi = n - 1;
        if (slo > shi) slo = shi;
        #pragma unroll 1
        while (slo < shi) {
            int mid = (slo + shi + 1) >> 1;
            if (__ldg(&rp[mid]) <= ec) slo = mid; else shi = mid - 1;
        }
        myrow = slo;
    }
    if (!valid) myrow = -1;
}

// ---------------------------------------------------------------------------
// Kernel 2: persistent edge-balanced aggregate. Warp processes chunks
// c = gwarp, gwarp+stride, ... Software pipeline per iteration:
//   PHASE A: issue 8 gather LDG.128s for current chunk (shfl redistribution)
//   STAGE  : load+search NEXT chunk (hides behind the in-flight gathers)
//   PHASE B: consume gathers, segmented accumulate, REDG.v4 flushes
// ---------------------------------------------------------------------------
__global__ void __launch_bounds__(256) gin_aggregate(
    const int* __restrict__ rp, const int* __restrict__ ci,
    float* __restrict__ out, int n, int nedges, int nchunks, int stride)
{
    int tid  = threadIdx.x;
    int lane = tid & 31;
    int grp  = lane >> 3, sub = lane & 7;
    int gwarp = blockIdx.x * 8 + (tid >> 5);

    if (gwarp >= nchunks) return;

    const ulonglong2* __restrict__ Y2 = (const ulonglong2*)g_Y;  // row = 8x16B

    int myc, myrow;
    stage_load(gwarp, lane, rp, ci, n, nedges, myc, myrow);

    for (int c = gwarp; c < nchunks; c += stride) {
        // PHASE A: batch all 8 independent gathers (1 LDG.128 = 4 edges/warp)
        ulonglong2 v[8];
        int rows[8];
        #pragma unroll
        for (int k = 0; k < 8; k++) {
            int src = grp * 8 + k;
            int cc  = __shfl_sync(0xffffffffu, myc,   src);
            rows[k] = __shfl_sync(0xffffffffu, myrow, src);
            v[k] = __ldg(&Y2[(size_t)cc * 8 + sub]);
        }

        // STAGE next chunk while gathers are in flight
        int cn = c + stride;
        int nmyc = 0, nmyrow = -1;
        if (cn < nchunks)
            stage_load(cn, lane, rp, ci, n, nedges, nmyc, nmyrow);

        // PHASE B: segmented accumulate over this group's 8 edges
        unsigned long long a01 = 0ull, a23 = 0ull;
        int cur = -1;
        #pragma unroll
        for (int k = 0; k < 8; k++) {
            int r = rows[k];
            if (r < 0) continue;                       // tail sentinel
            if (r != cur) {
                if (cur >= 0)
                    flush_v4(out + (size_t)cur * D + sub * 4, a01, a23);
                cur = r; a01 = 0ull; a23 = 0ull;
            }
            add2(a01, v[k].x);
            add2(a23, v[k].y);
        }
        if (cur >= 0)
            flush_v4(out + (size_t)cur * D + sub * 4, a01, a23);

        myc = nmyc; myrow = nmyrow;
    }
}

// ---------------------------------------------------------------------------
extern "C" void kernel_launch(void* const* d_in, const int* in_sizes, int n_in,
                              void* d_out, int out_size)
{
    const float* X  = (const float*)d_in[0];
    const float* W  = (const float*)d_in[1];
    const int*   rp = (const int*)d_in[2];
    const int*   ci = (const int*)d_in[3];
    float*       out = (float*)d_out;

    int n      = in_sizes[0] / D;   // number of nodes
    int nedges = in_sizes[3];       // E

    const int THREADS = 256;
    int tblocks = (n + 31) / 32;                 // transform: 4 rows/warp
    int nchunks = (nedges + 31) / 32;            // 32 edges per warp-iteration
    int wblocks = (nchunks + 255) / 256;         // warpstart role

    int ablocks = 1184;                          // persistent-ish: 8 per SM
    int awarps  = ablocks * (THREADS / 32);
    if (awarps > nchunks) {                      // small graphs: shrink
        ablocks = (nchunks + 7) / 8;
        awarps  = ablocks * (THREADS / 32);
    }

    gin_prep<<<tblocks + wblocks, THREADS>>>(X, W, rp, out, n, tblocks, nchunks);
    gin_aggregate<<<ablocks, THREADS>>>(rp, ci, out, n, nedges, nchunks, awarps);
}